// round 6
// baseline (speedup 1.0000x reference)
#include <cuda_runtime.h>
#include <cuda_bf16.h>
#include <math.h>
#include <cstdint>

#define S1 1024
#define SN 1024
#define DV 64
#define KM 32
#define NPIX (S1*SN)
#define YSEC 16

// ---------------- scratch (device globals; no allocations allowed) ----------
__device__ float g_v0[NPIX*DV];          // 268 MB ping
__device__ float g_v1[NPIX*DV];          // 268 MB pong
__device__ float g_Tre[KM*SN*DV];        // 8 MB
__device__ float g_Tim[KM*SN*DV];
__device__ float g_Gpre[YSEC*KM*KM*DV];  // 4 MB split-y partials
__device__ float g_Gpim[YSEC*KM*KM*DV];
__device__ float g_G2re[KM*KM*DV];
__device__ float g_G2im[KM*KM*DV];
__device__ float g_Hre[S1*KM*DV];        // 8 MB
__device__ float g_Him[S1*KM*DV];
__device__ float g_tc[KM*1024];          // cos(2*pi*k*n/1024)
__device__ float g_ts[KM*1024];          // sin(2*pi*k*n/1024)
__device__ __nv_bfloat16 g_Bhi[64*1024]; // twiddle rows for MMA: n<32 cos, n>=32 -sin
__device__ __nv_bfloat16 g_Blo[64*1024];

__device__ __forceinline__ float gelu_f(float x){
    return 0.5f * x * (1.0f + erff(x * 0.70710678118654752f));
}

// mma.sync m16n8k16 bf16 -> f32 (baseline PTX, works on compute_103)
#define MMA16816(D, A, B) \
    asm volatile("mma.sync.aligned.m16n8k16.row.col.f32.bf16.bf16.f32 " \
        "{%0,%1,%2,%3}, {%4,%5,%6,%7}, {%8,%9}, {%0,%1,%2,%3};" \
        : "+f"((D)[0]), "+f"((D)[1]), "+f"((D)[2]), "+f"((D)[3]) \
        : "r"((A)[0]), "r"((A)[1]), "r"((A)[2]), "r"((A)[3]), \
          "r"((B)[0]), "r"((B)[1]))

// ---------------- twiddle tables --------------------------------------------
__global__ void k_twiddle(){
    int idx = blockIdx.x * blockDim.x + threadIdx.x;
    if (idx < KM*1024){
        int k = idx >> 10, n = idx & 1023;
        int m = (k * n) & 1023;
        float s, c;
        sincospif((float)m * (1.0f/512.0f), &s, &c);
        g_tc[idx] = c;
        g_ts[idx] = s;
    }
    if (idx < 64*1024){
        int n = idx >> 10, x = idx & 1023;
        int m = ((n & 31) * x) & 1023;
        float s, c;
        sincospif((float)m * (1.0f/512.0f), &s, &c);
        float val = (n < 32) ? c : -s;
        __nv_bfloat16 h = __float2bfloat16(val);
        g_Bhi[idx] = h;
        g_Blo[idx] = __float2bfloat16(val - __bfloat162float(h));
    }
}

// ---------------- shallow: v = gelu(input @ Wsh + bsh) ----------------------
__global__ __launch_bounds__(256) void k_shallow(const float* __restrict__ in,
                                                 const float* __restrict__ Wsh,
                                                 const float* __restrict__ bsh){
    int idx = blockIdx.x * 256 + threadIdx.x;
    int c = idx & 63;
    int p = idx >> 6;
    float x = fmaf(in[2*p], Wsh[c], fmaf(in[2*p+1], Wsh[DV+c], bsh[c]));
    g_v0[idx] = gelu_f(x);
}

// ---------------- fwd1 (HMMA): T[n,col] = sum_x B[n,x] * v[x,col] -----------
// D[64 modes x 128 cols] per CTA; K=1024 in 16 chunks of 64.
// SMEM: A (twiddle) [64][pitch 72] bf16 hi/lo; B (v^T) [128][pitch 72] bf16 hi/lo.
// pitch 72 bf16 = 144 B -> fragment LDS bank = (36g+q) mod 32: conflict-free.
#define F1_AHI 0
#define F1_ALO 9216
#define F1_BHI 18432
#define F1_BLO 36864
#define F1_SMEM 55296

__global__ __launch_bounds__(256) void k_fwd1(int sel){
    const float* __restrict__ v = sel ? g_v1 : g_v0;
    extern __shared__ char sm[];
    __nv_bfloat16* aHi = (__nv_bfloat16*)(sm + F1_AHI);
    __nv_bfloat16* aLo = (__nv_bfloat16*)(sm + F1_ALO);
    __nv_bfloat16* bHi = (__nv_bfloat16*)(sm + F1_BHI);
    __nv_bfloat16* bLo = (__nv_bfloat16*)(sm + F1_BLO);

    int t = threadIdx.x, w = t >> 5, lane = t & 31;
    int g = lane >> 2, q = lane & 3;
    int colbase = blockIdx.x << 7;               // 128 cols per CTA

    float d[4][2][4];
    #pragma unroll
    for (int mt=0;mt<4;mt++)
        #pragma unroll
        for (int nt=0;nt<2;nt++)
            #pragma unroll
            for (int j=0;j<4;j++) d[mt][nt][j] = 0.f;

    for (int ch = 0; ch < 16; ch++){
        int x0 = ch << 6;
        // stage A: twiddles [64 modes][64 k] (2 bf16 per b32 copy)
        for (int i = t; i < 2048; i += 256){
            int n = i >> 5, k2 = (i & 31) << 1;
            *(uint32_t*)&aHi[n*72 + k2] = *(const uint32_t*)&g_Bhi[(n<<10) + x0 + k2];
            *(uint32_t*)&aLo[n*72 + k2] = *(const uint32_t*)&g_Blo[(n<<10) + x0 + k2];
        }
        // stage B: transpose v[x0:+64, colbase:+128] -> [col][x] bf16 hi/lo
        #pragma unroll
        for (int p = 0; p < 8; p++){
            int xl = (w << 3) + p;
            float4 f4 = *(const float4*)&v[(size_t)(x0+xl)*65536 + colbase + (lane<<2)];
            float fs[4] = {f4.x, f4.y, f4.z, f4.w};
            #pragma unroll
            for (int j = 0; j < 4; j++){
                int row = (lane<<2) + j;
                __nv_bfloat16 h = __float2bfloat16(fs[j]);
                __nv_bfloat16 l = __float2bfloat16(fs[j] - __bfloat162float(h));
                bHi[row*72 + xl] = h;
                bLo[row*72 + xl] = l;
            }
        }
        __syncthreads();
        #pragma unroll
        for (int ks = 0; ks < 4; ks++){
            int kb = ks << 4;
            uint32_t AH[4][4], AL[4][4], BH[2][2], BL[2][2];
            #pragma unroll
            for (int mt = 0; mt < 4; mt++){
                int r0 = (mt<<4) + g;
                int c0 = kb + (q<<1);
                AH[mt][0] = *(uint32_t*)&aHi[r0*72 + c0];
                AH[mt][1] = *(uint32_t*)&aHi[(r0+8)*72 + c0];
                AH[mt][2] = *(uint32_t*)&aHi[r0*72 + c0 + 8];
                AH[mt][3] = *(uint32_t*)&aHi[(r0+8)*72 + c0 + 8];
                AL[mt][0] = *(uint32_t*)&aLo[r0*72 + c0];
                AL[mt][1] = *(uint32_t*)&aLo[(r0+8)*72 + c0];
                AL[mt][2] = *(uint32_t*)&aLo[r0*72 + c0 + 8];
                AL[mt][3] = *(uint32_t*)&aLo[(r0+8)*72 + c0 + 8];
            }
            #pragma unroll
            for (int nt = 0; nt < 2; nt++){
                int n = (w<<4) + (nt<<3) + g;
                int k0 = kb + (q<<1);
                BH[nt][0] = *(uint32_t*)&bHi[n*72 + k0];
                BH[nt][1] = *(uint32_t*)&bHi[n*72 + k0 + 8];
                BL[nt][0] = *(uint32_t*)&bLo[n*72 + k0];
                BL[nt][1] = *(uint32_t*)&bLo[n*72 + k0 + 8];
            }
            #pragma unroll
            for (int mt = 0; mt < 4; mt++)
                #pragma unroll
                for (int nt = 0; nt < 2; nt++){
                    MMA16816(d[mt][nt], AH[mt], BH[nt]);
                    MMA16816(d[mt][nt], AH[mt], BL[nt]);
                    MMA16816(d[mt][nt], AL[mt], BH[nt]);
                }
        }
        __syncthreads();
    }
    // writeout: rows 0..31 -> Tre, 32..63 -> Tim
    #pragma unroll
    for (int mt = 0; mt < 4; mt++){
        float* T = (mt < 2) ? g_Tre : g_Tim;
        int rr = ((mt & 1) << 4) + g;
        #pragma unroll
        for (int nt = 0; nt < 2; nt++){
            int col = colbase + (w<<4) + (nt<<3) + (q<<1);
            T[(rr<<16) + col]       = d[mt][nt][0];
            T[(rr<<16) + col + 1]   = d[mt][nt][1];
            T[((rr+8)<<16) + col]   = d[mt][nt][2];
            T[((rr+8)<<16) + col+1] = d[mt][nt][3];
        }
    }
}

// ---------------- fwd2 (split-y): partial G over 64-y sections --------------
__global__ __launch_bounds__(256) void k_fwd2(){
    int k1 = blockIdx.x;            // 32
    int ys = blockIdx.y;            // YSEC=16
    int y0 = ys << 6;
    __shared__ float str[32][64], sti[32][64];
    __shared__ float swc[32][64], sws[32][64];   // [k2][y-local]
    int t = threadIdx.x, q = t >> 6, c = t & 63;

    for (int i = t; i < 2048; i += 256){
        int k2 = i >> 6, yy = i & 63;
        swc[k2][yy] = g_tc[(k2<<10) + y0 + yy];
        sws[k2][yy] = g_ts[(k2<<10) + y0 + yy];
    }
    float ar[8], ai[8];
    #pragma unroll
    for (int j = 0; j < 8; j++){ ar[j] = 0.f; ai[j] = 0.f; }

    for (int half = 0; half < 2; half++){
        int yb = y0 + (half << 5);
        __syncthreads();
        for (int i = t; i < 2048; i += 256){
            int yy = i >> 6, cc = i & 63;
            str[yy][cc] = g_Tre[(k1<<16) + ((yb+yy)<<6) + cc];
            sti[yy][cc] = g_Tim[(k1<<16) + ((yb+yy)<<6) + cc];
        }
        __syncthreads();
        #pragma unroll 4
        for (int yy = 0; yy < 32; yy++){
            float r = str[yy][c], m = sti[yy][c];
            #pragma unroll
            for (int j = 0; j < 8; j++){
                int k2 = (q<<3) + j;
                float cc_ = swc[k2][(half<<5)+yy], s_ = sws[k2][(half<<5)+yy];
                ar[j] = fmaf(r, cc_, fmaf(m,  s_, ar[j]));
                ai[j] = fmaf(m, cc_, fmaf(-r, s_, ai[j]));
            }
        }
    }
    #pragma unroll
    for (int j = 0; j < 8; j++){
        int k2 = (q<<3) + j;
        int o = ((ys<<10) + (k1<<5) + k2)*64 + c;
        g_Gpre[o] = ar[j];
        g_Gpim[o] = ai[j];
    }
}

// ---------------- R multiply (with partial reduction) -----------------------
__global__ __launch_bounds__(64) void k_rmul(const float* __restrict__ Rr,
                                             const float* __restrict__ Ri){
    int kk = blockIdx.x;              // k1*32+k2
    int d  = threadIdx.x;
    __shared__ float sgr[64], sgi[64];
    float gr = 0.f, gi = 0.f;
    #pragma unroll
    for (int ys = 0; ys < YSEC; ys++){
        gr += g_Gpre[((ys<<10) + kk)*64 + d];
        gi += g_Gpim[((ys<<10) + kk)*64 + d];
    }
    sgr[d] = gr;
    sgi[d] = gi;
    __syncthreads();
    const float* rr = Rr + kk*4096;
    const float* ri = Ri + kk*4096;
    float ar = 0.f, ai = 0.f;
    #pragma unroll 4
    for (int c = 0; c < 64; c++){
        float a = sgr[c], b = sgi[c];
        float x = rr[c*64 + d], y = ri[c*64 + d];
        ar = fmaf(a, x, fmaf(-b, y, ar));
        ai = fmaf(a, y, fmaf( b, x, ai));
    }
    int k2 = kk & 31;
    float scl = (k2 == 0 ? 1.0f : 2.0f) * (1.0f/1048576.0f);
    g_G2re[kk*64 + d] = ar * scl;
    g_G2im[kk*64 + d] = ai * scl;
}

// ---------------- inv1: H[x,k2,c] = sum_k1 G2[k1,k2,c]*e^{+2pi i k1 x/N} ----
__global__ __launch_bounds__(256) void k_inv1(){
    int t  = threadIdx.x;
    int x0 = blockIdx.x << 2;
    __shared__ float sc[4][32], ss[4][32];
    if (t < 128){
        int xx = t >> 5, kk = t & 31;
        sc[xx][kk] = g_tc[kk*1024 + x0 + xx];
        ss[xx][kk] = g_ts[kk*1024 + x0 + xx];
    }
    __syncthreads();
    float aR[4][8], aI[4][8];
    #pragma unroll
    for (int xx=0;xx<4;xx++)
        #pragma unroll
        for (int i=0;i<8;i++){ aR[xx][i]=0.f; aI[xx][i]=0.f; }

    for (int k1=0; k1<KM; k1++){
        float gr[8], gi[8];
        #pragma unroll
        for (int i=0;i<8;i++){
            gr[i] = g_G2re[k1*2048 + t + (i<<8)];
            gi[i] = g_G2im[k1*2048 + t + (i<<8)];
        }
        #pragma unroll
        for (int xx=0;xx<4;xx++){
            float c_ = sc[xx][k1], s_ = ss[xx][k1];
            #pragma unroll
            for (int i=0;i<8;i++){
                aR[xx][i] = fmaf(gr[i], c_, fmaf(-gi[i], s_, aR[xx][i]));
                aI[xx][i] = fmaf(gr[i], s_, fmaf( gi[i], c_, aI[xx][i]));
            }
        }
    }
    #pragma unroll
    for (int xx=0;xx<4;xx++)
        #pragma unroll
        for (int i=0;i<8;i++){
            g_Hre[(x0+xx)*2048 + t + (i<<8)] = aR[xx][i];
            g_Him[(x0+xx)*2048 + t + (i<<8)] = aI[xx][i];
        }
}

// ---------------- inv2 fused: out = gelu( irfft-part + v @ w ) --------------
__global__ __launch_bounds__(256) void k_inv2(int sel, const float* __restrict__ w){
    const float* __restrict__ v   = sel ? g_v1 : g_v0;
    float*       __restrict__ out = sel ? g_v0 : g_v1;
    int x  = blockIdx.y;
    int y0 = blockIdx.x << 6;
    int t  = threadIdx.x;
    int tc = t & 15, ty = t >> 4;

    float acc[4][4];
    #pragma unroll
    for (int i=0;i<4;i++)
        #pragma unroll
        for (int j=0;j<4;j++) acc[i][j] = 0.f;

    const float* vb = v + ((x<<10) + y0)*64;
    #pragma unroll 4
    for (int d=0; d<64; d+=4){
        float4 va[4];
        #pragma unroll
        for (int i=0;i<4;i++) va[i] = *(const float4*)&vb[((ty<<2)+i)*64 + d];
        float4 w0 = *(const float4*)&w[(d+0)*64 + (tc<<2)];
        float4 w1 = *(const float4*)&w[(d+1)*64 + (tc<<2)];
        float4 w2 = *(const float4*)&w[(d+2)*64 + (tc<<2)];
        float4 w3 = *(const float4*)&w[(d+3)*64 + (tc<<2)];
        #pragma unroll
        for (int i=0;i<4;i++){
            acc[i][0] = fmaf(va[i].x,w0.x,fmaf(va[i].y,w1.x,fmaf(va[i].z,w2.x,fmaf(va[i].w,w3.x,acc[i][0]))));
            acc[i][1] = fmaf(va[i].x,w0.y,fmaf(va[i].y,w1.y,fmaf(va[i].z,w2.y,fmaf(va[i].w,w3.y,acc[i][1]))));
            acc[i][2] = fmaf(va[i].x,w0.z,fmaf(va[i].y,w1.z,fmaf(va[i].z,w2.z,fmaf(va[i].w,w3.z,acc[i][2]))));
            acc[i][3] = fmaf(va[i].x,w0.w,fmaf(va[i].y,w1.w,fmaf(va[i].z,w2.w,fmaf(va[i].w,w3.w,acc[i][3]))));
        }
    }

    const float* hr = g_Hre + x*2048;
    const float* hi = g_Him + x*2048;
    #pragma unroll 4
    for (int k2=0; k2<32; k2++){
        float4 r4 = *(const float4*)&hr[(k2<<6) + (tc<<2)];
        float4 i4 = *(const float4*)&hi[(k2<<6) + (tc<<2)];
        float4 c4 = *(const float4*)&g_tc[(k2<<10) + y0 + (ty<<2)];
        float4 s4 = *(const float4*)&g_ts[(k2<<10) + y0 + (ty<<2)];
        float rr[4] = {r4.x,r4.y,r4.z,r4.w};
        float ii[4] = {i4.x,i4.y,i4.z,i4.w};
        float cc[4] = {c4.x,c4.y,c4.z,c4.w};
        float sn[4] = {s4.x,s4.y,s4.z,s4.w};
        #pragma unroll
        for (int i=0;i<4;i++)
            #pragma unroll
            for (int j=0;j<4;j++)
                acc[i][j] = fmaf(rr[j], cc[i], fmaf(-ii[j], sn[i], acc[i][j]));
    }

    #pragma unroll
    for (int i=0;i<4;i++){
        float4 o;
        o.x = gelu_f(acc[i][0]);
        o.y = gelu_f(acc[i][1]);
        o.z = gelu_f(acc[i][2]);
        o.w = gelu_f(acc[i][3]);
        *(float4*)&out[((x<<10) + y0 + (ty<<2) + i)*64 + (tc<<2)] = o;
    }
}

// ---------------- projection: out[x,y] = v . Wp + bp ------------------------
__global__ __launch_bounds__(256) void k_proj(int sel, const float* __restrict__ Wp,
                                              const float* __restrict__ bp,
                                              float* __restrict__ out){
    const float* __restrict__ v = sel ? g_v1 : g_v0;
    int gw   = (blockIdx.x * 256 + threadIdx.x) >> 5;
    int lane = threadIdx.x & 31;
    const float* vp = v + gw*64;
    float s = fmaf(vp[lane], Wp[lane], vp[lane+32]*Wp[lane+32]);
    #pragma unroll
    for (int o=16;o;o>>=1) s += __shfl_down_sync(0xffffffffu, s, o);
    if (lane == 0) out[gw] = s + bp[0];
}

// ---------------- launcher --------------------------------------------------
extern "C" void kernel_launch(void* const* d_in, const int* in_sizes, int n_in,
                              void* d_out, int out_size){
    const float* input = (const float*)d_in[0];
    const float* Wsh   = (const float*)d_in[1];
    const float* bsh   = (const float*)d_in[2];
    const float* Rr[4] = {(const float*)d_in[3],(const float*)d_in[6],
                          (const float*)d_in[9],(const float*)d_in[12]};
    const float* Ri[4] = {(const float*)d_in[4],(const float*)d_in[7],
                          (const float*)d_in[10],(const float*)d_in[13]};
    const float* ww[4] = {(const float*)d_in[5],(const float*)d_in[8],
                          (const float*)d_in[11],(const float*)d_in[14]};
    const float* Wp = (const float*)d_in[15];
    const float* bp = (const float*)d_in[16];
    float* out = (float*)d_out;

    cudaFuncSetAttribute(k_fwd1, cudaFuncAttributeMaxDynamicSharedMemorySize, F1_SMEM);

    k_twiddle<<<256, 256>>>();
    k_shallow<<<(NPIX*DV)/256, 256>>>(input, Wsh, bsh);

    int cur = 0;   // g_v0 holds current activation
    for (int l=0; l<4; l++){
        k_fwd1<<<512, 256, F1_SMEM>>>(cur);
        k_fwd2<<<dim3(32, YSEC), 256>>>();
        k_rmul<<<1024, 64>>>(Rr[l], Ri[l]);
        k_inv1<<<256, 256>>>();
        k_inv2<<<dim3(16,1024), 256>>>(cur, ww[l]);
        cur ^= 1;
    }
    k_proj<<<NPIX/8, 256>>>(cur, Wp, bp, out);
}